// round 8
// baseline (speedup 1.0000x reference)
#include <cuda_runtime.h>

#define NPTS 65536
#define NSMP 16
#define NSAMPLES (NPTS * NSMP)
#define CNT ((float)NSAMPLES)
#define EPS 1e-5f

// ---------------- static device scratch ------------------------------------
__device__ float g_xq[NPTS * 64];
__device__ float g_xk[NPTS * 64];
__device__ float g_xv[NPTS * 64];
__device__ float g_w8[NSAMPLES * 8];
__device__ float g_r0[NSAMPLES];   // positional activations, plane per channel
__device__ float g_r1[NSAMPLES];
__device__ float g_r2[NSAMPLES];
__device__ float g_sP[6];          // sum[3], sumsq[3]
__device__ float g_sW1[128];       // sum[64], sumsq[64]
__device__ float g_sW2[16];        // sum[8],  sumsq[8]

// ---------------- f32x2 helpers ---------------------------------------------
typedef unsigned long long ull;
__device__ __forceinline__ ull fma2(ull a, ull b, ull c) {
    ull d;
    asm("fma.rn.f32x2 %0, %1, %2, %3;" : "=l"(d) : "l"(a), "l"(b), "l"(c));
    return d;
}
__device__ __forceinline__ ull dup2(float v) {
    ull d;
    asm("mov.b64 %0, {%1, %1};" : "=l"(d) : "r"(__float_as_uint(v)));
    return d;
}
__device__ __forceinline__ void unpack2(ull v, float& lo, float& hi) {
    unsigned int a, b;
    asm("mov.b64 {%0, %1}, %2;" : "=r"(a), "=r"(b) : "l"(v));
    lo = __uint_as_float(a); hi = __uint_as_float(b);
}

// ---------------- K0: zero stats --------------------------------------------
__global__ void k_zero() {
    int t = threadIdx.x;
    if (t < 6)   g_sP[t]  = 0.f;
    if (t < 128) g_sW1[t] = 0.f;
    if (t < 16)  g_sW2[t] = 0.f;
}

// ---------------- K1: QKV GEMM (f32x2 packed) --------------------------------
// grid (1024, 3); block 256. Tile: 64 points x 64 out-channels.
__global__ __launch_bounds__(256) void k_gemm(
    const float* __restrict__ x,
    const float* __restrict__ Wq, const float* __restrict__ bq,
    const float* __restrict__ Wk, const float* __restrict__ bk,
    const float* __restrict__ Wv, const float* __restrict__ bv) {
    __shared__ float xs[64 * 68];  // [j][point]
    __shared__ float ws[64 * 68];  // [j][outch]
    const int t = threadIdx.x;
    const int m = blockIdx.y;
    const float* W    = (m == 0) ? Wq : ((m == 1) ? Wk : Wv);
    const float* bias = (m == 0) ? bq : ((m == 1) ? bk : bv);
    float* out        = (m == 0) ? g_xq : ((m == 1) ? g_xk : g_xv);
    const int pbase = blockIdx.x * 64;

    for (int e = t; e < 4096; e += 256) {
        int r = e >> 6, j = e & 63;
        xs[j * 68 + r] = x[(pbase + r) * 64 + j];
        ws[j * 68 + r] = W[r * 64 + j];
    }
    __syncthreads();

    const int tx = t & 15;   // channels tx*4 .. +3  (2 packed pairs)
    const int ty = t >> 4;   // points   ty*4 .. +3
    ull acc[4][2];
#pragma unroll
    for (int i = 0; i < 4; i++) { acc[i][0] = 0ULL; acc[i][1] = 0ULL; }

    const float4* xp = (const float4*)(xs + ty * 4);
#pragma unroll 8
    for (int j = 0; j < 64; j++) {
        float4 xv4 = xp[j * 17];
        ulonglong2 w2 = *(const ulonglong2*)(ws + j * 68 + tx * 4);
        ull X;
        X = dup2(xv4.x); acc[0][0] = fma2(X, w2.x, acc[0][0]); acc[0][1] = fma2(X, w2.y, acc[0][1]);
        X = dup2(xv4.y); acc[1][0] = fma2(X, w2.x, acc[1][0]); acc[1][1] = fma2(X, w2.y, acc[1][1]);
        X = dup2(xv4.z); acc[2][0] = fma2(X, w2.x, acc[2][0]); acc[2][1] = fma2(X, w2.y, acc[2][1]);
        X = dup2(xv4.w); acc[3][0] = fma2(X, w2.x, acc[3][0]); acc[3][1] = fma2(X, w2.y, acc[3][1]);
    }

    float4 bo = *(const float4*)(bias + tx * 4);
#pragma unroll
    for (int pp = 0; pp < 4; pp++) {
        float c0, c1, c2, c3;
        unpack2(acc[pp][0], c0, c1);
        unpack2(acc[pp][1], c2, c3);
        *(float4*)(out + (pbase + ty * 4 + pp) * 64 + tx * 4) =
            make_float4(c0 + bo.x, c1 + bo.y, c2 + bo.z, c3 + bo.w);
    }
}

// ---------------- K2: positional pre-BN activations + stats ------------------
// grid 1024; block 256; thread handles 4 consecutive samples.
__global__ __launch_bounds__(256) void k_statsP(
    const float* __restrict__ p, const int* __restrict__ idx,
    const float* __restrict__ Wp1, const float* __restrict__ bp1) {
    float w00 = Wp1[0], w01 = Wp1[1], w02 = Wp1[2];
    float w10 = Wp1[3], w11 = Wp1[4], w12 = Wp1[5];
    float w20 = Wp1[6], w21 = Wp1[7], w22 = Wp1[8];
    float b0 = bp1[0], b1 = bp1[1], b2 = bp1[2];

    float s0 = 0, s1 = 0, s2 = 0, q0 = 0, q1 = 0, q2 = 0;
    int base = (blockIdx.x * 256 + threadIdx.x) * 4;
    int4 jj = *(const int4*)(idx + base);
    int js[4] = {jj.x, jj.y, jj.z, jj.w};
    float o0[4], o1[4], o2[4];
#pragma unroll
    for (int i = 0; i < 4; i++) {
        int sid = base + i;
        int n = sid >> 4;
        int j = js[i];
        float dx = p[j * 3 + 0] - p[n * 3 + 0];
        float dy = p[j * 3 + 1] - p[n * 3 + 1];
        float dz = p[j * 3 + 2] - p[n * 3 + 2];
        float a0 = w00 * dx + w01 * dy + w02 * dz + b0;
        float a1 = w10 * dx + w11 * dy + w12 * dz + b1;
        float a2 = w20 * dx + w21 * dy + w22 * dz + b2;
        o0[i] = a0; o1[i] = a1; o2[i] = a2;
        s0 += a0; s1 += a1; s2 += a2;
        q0 += a0 * a0; q1 += a1 * a1; q2 += a2 * a2;
    }
    *(float4*)(g_r0 + base) = make_float4(o0[0], o0[1], o0[2], o0[3]);
    *(float4*)(g_r1 + base) = make_float4(o1[0], o1[1], o1[2], o1[3]);
    *(float4*)(g_r2 + base) = make_float4(o2[0], o2[1], o2[2], o2[3]);

#pragma unroll
    for (int o = 16; o; o >>= 1) {
        s0 += __shfl_xor_sync(0xffffffffu, s0, o);
        s1 += __shfl_xor_sync(0xffffffffu, s1, o);
        s2 += __shfl_xor_sync(0xffffffffu, s2, o);
        q0 += __shfl_xor_sync(0xffffffffu, q0, o);
        q1 += __shfl_xor_sync(0xffffffffu, q1, o);
        q2 += __shfl_xor_sync(0xffffffffu, q2, o);
    }
    __shared__ float red[8][6];
    int w = threadIdx.x >> 5, lane = threadIdx.x & 31;
    if (lane == 0) {
        red[w][0] = s0; red[w][1] = s1; red[w][2] = s2;
        red[w][3] = q0; red[w][4] = q1; red[w][5] = q2;
    }
    __syncthreads();
    if (threadIdx.x < 6) {
        float acc = 0.f;
#pragma unroll
        for (int i = 0; i < 8; i++) acc += red[i][threadIdx.x];
        atomicAdd(&g_sP[threadIdx.x], acc);
    }
}

// ---------------- K2b: apply BN+ReLU to r planes in place --------------------
// grid (1024, 3); block 256; float4 per thread.
__global__ __launch_bounds__(256) void k_bnp(
    const float* __restrict__ gp, const float* __restrict__ betap) {
    int c = blockIdx.y;
    float m = g_sP[c] / CNT;
    float v = g_sP[3 + c] / CNT - m * m;
    float A = gp[c] * rsqrtf(v + EPS);
    float B = betap[c] - m * A;
    float* r = (c == 0) ? g_r0 : ((c == 1) ? g_r1 : g_r2);
    int i = (blockIdx.x * 256 + threadIdx.x) * 4;
    float4 v4 = *(float4*)(r + i);
    v4.x = fmaxf(A * v4.x + B, 0.f);
    v4.y = fmaxf(A * v4.y + B, 0.f);
    v4.z = fmaxf(A * v4.z + B, 0.f);
    v4.w = fmaxf(A * v4.w + B, 0.f);
    *(float4*)(r + i) = v4;
}

// ---------------- K3: stats of w = xk[idx] - xq + p_r2 -----------------------
// grid 1024; block 256 (8 warps); warp handles 8 points.
__global__ __launch_bounds__(256) void k_statsW1(
    const int* __restrict__ idx,
    const float* __restrict__ Wp2, const float* __restrict__ bp2) {
    __shared__ float sh_r[8][16][3];
    __shared__ int   sh_j[8][16];
    __shared__ float sred[128];
    int t = threadIdx.x, w = t >> 5, l = t & 31;
    if (t < 128) sred[t] = 0.f;

    int c0 = l, c1 = l + 32;
    float wa0 = Wp2[c0 * 3], wa1 = Wp2[c0 * 3 + 1], wa2 = Wp2[c0 * 3 + 2], ba = bp2[c0];
    float wb0 = Wp2[c1 * 3], wb1 = Wp2[c1 * 3 + 1], wb2 = Wp2[c1 * 3 + 2], bb = bp2[c1];

    float s0 = 0, ss0 = 0, s1 = 0, ss1 = 0;
    int pwarp = (blockIdx.x * 8 + w) * 8;
    __syncthreads();

    for (int pt = 0; pt < 8; pt++) {
        int n = pwarp + pt;
        float xq0 = g_xq[n * 64 + c0];
        float xq1 = g_xq[n * 64 + c1];
        if (l < 16) {
            int sid = n * 16 + l;
            sh_j[w][l] = idx[sid];
            sh_r[w][l][0] = g_r0[sid];
            sh_r[w][l][1] = g_r1[sid];
            sh_r[w][l][2] = g_r2[sid];
        }
        __syncwarp();
#pragma unroll
        for (int k = 0; k < 16; k++) {
            int j = sh_j[w][k];
            float r0 = sh_r[w][k][0], r1 = sh_r[w][k][1], r2 = sh_r[w][k][2];
            float pr0 = ba + r0 * wa0 + r1 * wa1 + r2 * wa2;
            float pr1 = bb + r0 * wb0 + r1 * wb1 + r2 * wb2;
            float v0 = g_xk[j * 64 + c0] - xq0 + pr0;
            float v1 = g_xk[j * 64 + c1] - xq1 + pr1;
            s0 += v0; ss0 += v0 * v0;
            s1 += v1; ss1 += v1 * v1;
        }
        __syncwarp();
    }
    atomicAdd(&sred[c0], s0);
    atomicAdd(&sred[64 + c0], ss0);
    atomicAdd(&sred[c1], s1);
    atomicAdd(&sred[64 + c1], ss1);
    __syncthreads();
    if (t < 128) atomicAdd(&g_sW1[t], sred[t]);
}

// ---------------- K4: w8 = relu(bn1(w)) @ Ww1^T + bw1, + stats ---------------
// grid 2048; block 128 (4 warps); warp handles 8 points in 4 tiles of 2.
__global__ __launch_bounds__(128) void k_w8(
    const int* __restrict__ idx,
    const float* __restrict__ Wp2, const float* __restrict__ bp2,
    const float* __restrict__ gw1, const float* __restrict__ betaw1,
    const float* __restrict__ Ww1, const float* __restrict__ bw1) {
    __shared__ float sh_h[4][32 * 68];
    __shared__ float sh_r[4][32][3];
    __shared__ int   sh_j[4][32];
    __shared__ float ww1s[8][64];
    __shared__ float sred2[16];
    int t = threadIdx.x, w = t >> 5, l = t & 31;
    if (t < 16) sred2[t] = 0.f;
    for (int e = t; e < 512; e += 128) ww1s[e >> 6][e & 63] = Ww1[e];

    int c0 = l, c1 = l + 32;
    float wa0 = Wp2[c0 * 3], wa1 = Wp2[c0 * 3 + 1], wa2 = Wp2[c0 * 3 + 2], ba = bp2[c0];
    float wb0 = Wp2[c1 * 3], wb1 = Wp2[c1 * 3 + 1], wb2 = Wp2[c1 * 3 + 2], bb = bp2[c1];

    float m0 = g_sW1[c0] / CNT, v0 = g_sW1[64 + c0] / CNT - m0 * m0;
    float A0 = gw1[c0] * rsqrtf(v0 + EPS), B0 = betaw1[c0] - m0 * A0;
    float m1 = g_sW1[c1] / CNT, v1 = g_sW1[64 + c1] / CNT - m1 * m1;
    float A1 = gw1[c1] * rsqrtf(v1 + EPS), B1 = betaw1[c1] - m1 * A1;

    float bw[8];
#pragma unroll
    for (int r = 0; r < 8; r++) bw[r] = bw1[r];
    float sw[8], sq[8];
#pragma unroll
    for (int r = 0; r < 8; r++) { sw[r] = 0.f; sq[r] = 0.f; }

    int pwarp = (blockIdx.x * 4 + w) * 8;
    __syncthreads();

    for (int tt = 0; tt < 4; tt++) {
        int pA = pwarp + tt * 2;
        {   // stage 2 points x 16 neighbors
            int sid = (pA + (l >> 4)) * 16 + (l & 15);
            sh_j[w][l] = idx[sid];
            sh_r[w][l][0] = g_r0[sid];
            sh_r[w][l][1] = g_r1[sid];
            sh_r[w][l][2] = g_r2[sid];
        }
        float xqA0 = g_xq[pA * 64 + c0],       xqA1 = g_xq[pA * 64 + c1];
        float xqB0 = g_xq[(pA + 1) * 64 + c0], xqB1 = g_xq[(pA + 1) * 64 + c1];
        __syncwarp();
#pragma unroll
        for (int k = 0; k < 32; k++) {
            int j = sh_j[w][k];
            float r0 = sh_r[w][k][0], r1 = sh_r[w][k][1], r2 = sh_r[w][k][2];
            float pr0 = ba + r0 * wa0 + r1 * wa1 + r2 * wa2;
            float pr1 = bb + r0 * wb0 + r1 * wb1 + r2 * wb2;
            float xq0_ = (k < 16) ? xqA0 : xqB0;
            float xq1_ = (k < 16) ? xqA1 : xqB1;
            float u0 = g_xk[j * 64 + c0] - xq0_ + pr0;
            float u1 = g_xk[j * 64 + c1] - xq1_ + pr1;
            sh_h[w][k * 68 + l]      = fmaxf(A0 * u0 + B0, 0.f);
            sh_h[w][k * 68 + l + 32] = fmaxf(A1 * u1 + B1, 0.f);
        }
        __syncwarp();
        // lane <-> sample; matvec 64 -> 8
        float y[8];
#pragma unroll
        for (int r = 0; r < 8; r++) y[r] = bw[r];
        const float4* hv4 = (const float4*)(sh_h[w] + l * 68);
#pragma unroll
        for (int cc = 0; cc < 16; cc++) {
            float4 h4 = hv4[cc];
#pragma unroll
            for (int r = 0; r < 8; r++) {
                float4 w4 = *(const float4*)(&ww1s[r][cc * 4]);
                y[r] += h4.x * w4.x + h4.y * w4.y + h4.z * w4.z + h4.w * w4.w;
            }
        }
        int sid = pA * 16 + l;
        *(float4*)(g_w8 + sid * 8)     = make_float4(y[0], y[1], y[2], y[3]);
        *(float4*)(g_w8 + sid * 8 + 4) = make_float4(y[4], y[5], y[6], y[7]);
#pragma unroll
        for (int r = 0; r < 8; r++) { sw[r] += y[r]; sq[r] += y[r] * y[r]; }
        __syncwarp();
    }
#pragma unroll
    for (int o = 16; o; o >>= 1) {
#pragma unroll
        for (int r = 0; r < 8; r++) {
            sw[r] += __shfl_xor_sync(0xffffffffu, sw[r], o);
            sq[r] += __shfl_xor_sync(0xffffffffu, sq[r], o);
        }
    }
    if (l == 0) {
#pragma unroll
        for (int r = 0; r < 8; r++) {
            atomicAdd(&sred2[r], sw[r]);
            atomicAdd(&sred2[8 + r], sq[r]);
        }
    }
    __syncthreads();
    if (t < 16) atomicAdd(&g_sW2[t], sred2[t]);
}

// ---------------- K5: bn2 + relu + 8x8 matvec + softmax + aggregate ----------
// grid 4096; block 256 (8 warps); warp handles 2 points.
__global__ __launch_bounds__(256) void k_final(
    const int* __restrict__ idx,
    const float* __restrict__ Wp2, const float* __restrict__ bp2,
    const float* __restrict__ gw2, const float* __restrict__ betaw2,
    const float* __restrict__ Ww2, const float* __restrict__ bw2,
    float* __restrict__ out) {
    __shared__ float sh_s[8][32][9];
    __shared__ float sh_r[8][32][3];
    __shared__ int   sh_j[8][32];
    int t = threadIdx.x, w = t >> 5, l = t & 31;

    float A2[8], B2[8];
#pragma unroll
    for (int r = 0; r < 8; r++) {
        float m = g_sW2[r] / CNT;
        float v = g_sW2[8 + r] / CNT - m * m;
        A2[r] = gw2[r] * rsqrtf(v + EPS);
        B2[r] = betaw2[r] - m * A2[r];
    }

    int c0 = l, c1 = l + 32;
    float wa0 = Wp2[c0 * 3], wa1 = Wp2[c0 * 3 + 1], wa2 = Wp2[c0 * 3 + 2], ba = bp2[c0];
    float wb0 = Wp2[c1 * 3], wb1 = Wp2[c1 * 3 + 1], wb2 = Wp2[c1 * 3 + 2], bb = bp2[c1];

    int pbase = (blockIdx.x * 8 + w) * 2;
    int sid = (pbase + (l >> 4)) * 16 + (l & 15);
    sh_j[w][l] = idx[sid];
    sh_r[w][l][0] = g_r0[sid];
    sh_r[w][l][1] = g_r1[sid];
    sh_r[w][l][2] = g_r2[sid];

    float4 y0 = *(const float4*)(g_w8 + sid * 8);
    float4 y1 = *(const float4*)(g_w8 + sid * 8 + 4);
    float h[8] = {y0.x, y0.y, y0.z, y0.w, y1.x, y1.y, y1.z, y1.w};
#pragma unroll
    for (int r = 0; r < 8; r++) h[r] = fmaxf(A2[r] * h[r] + B2[r], 0.f);

    float z[8];
#pragma unroll
    for (int r = 0; r < 8; r++) {
        float acc = bw2[r];
#pragma unroll
        for (int i = 0; i < 8; i++) acc += h[i] * Ww2[r * 8 + i];
        z[r] = acc;
    }
    // softmax over 16 neighbors (xor <= 8 keeps 16-lane halves independent)
#pragma unroll
    for (int r = 0; r < 8; r++) {
        float mx = z[r];
#pragma unroll
        for (int o = 8; o; o >>= 1) mx = fmaxf(mx, __shfl_xor_sync(0xffffffffu, mx, o));
        float e = __expf(z[r] - mx);
        float sm = e;
#pragma unroll
        for (int o = 8; o; o >>= 1) sm += __shfl_xor_sync(0xffffffffu, sm, o);
        sh_s[w][l][r] = e / sm;
    }
    __syncwarp();
#pragma unroll
    for (int pp = 0; pp < 2; pp++) {
        int n = pbase + pp;
        float acc0 = 0.f, acc1 = 0.f;
#pragma unroll
        for (int k = 0; k < 16; k++) {
            int kk = pp * 16 + k;
            int jg = sh_j[w][kk];
            float r0 = sh_r[w][kk][0], r1 = sh_r[w][kk][1], r2 = sh_r[w][kk][2];
            float pr0 = ba + r0 * wa0 + r1 * wa1 + r2 * wa2;
            float pr1 = bb + r0 * wb0 + r1 * wb1 + r2 * wb2;
            float s8 = sh_s[w][kk][l & 7];
            acc0 += (g_xv[jg * 64 + c0] + pr0) * s8;
            acc1 += (g_xv[jg * 64 + c1] + pr1) * s8;
        }
        out[n * 64 + c0] = acc0;
        out[n * 64 + c1] = acc1;
    }
}

// ---------------- launch ------------------------------------------------------
extern "C" void kernel_launch(void* const* d_in, const int* in_sizes, int n_in,
                              void* d_out, int out_size) {
    const float* p     = (const float*)d_in[0];
    const float* x     = (const float*)d_in[1];
    const int*   idx   = (const int*)d_in[2];
    const float* Wq    = (const float*)d_in[3];
    const float* bq    = (const float*)d_in[4];
    const float* Wk    = (const float*)d_in[5];
    const float* bk    = (const float*)d_in[6];
    const float* Wv    = (const float*)d_in[7];
    const float* bv    = (const float*)d_in[8];
    const float* Wp1   = (const float*)d_in[9];
    const float* bp1   = (const float*)d_in[10];
    const float* gp    = (const float*)d_in[11];
    const float* betap = (const float*)d_in[12];
    const float* Wp2   = (const float*)d_in[13];
    const float* bp2   = (const float*)d_in[14];
    const float* gw1   = (const float*)d_in[15];
    const float* betaw1= (const float*)d_in[16];
    const float* Ww1   = (const float*)d_in[17];
    const float* bw1   = (const float*)d_in[18];
    const float* gw2   = (const float*)d_in[19];
    const float* betaw2= (const float*)d_in[20];
    const float* Ww2   = (const float*)d_in[21];
    const float* bw2   = (const float*)d_in[22];
    float* out = (float*)d_out;

    k_zero<<<1, 128>>>();
    dim3 g1(1024, 3);
    k_gemm<<<g1, 256>>>(x, Wq, bq, Wk, bk, Wv, bv);
    k_statsP<<<1024, 256>>>(p, idx, Wp1, bp1);
    dim3 g2(1024, 3);
    k_bnp<<<g2, 256>>>(gp, betap);
    k_statsW1<<<1024, 256>>>(idx, Wp2, bp2);
    k_w8<<<2048, 128>>>(idx, Wp2, bp2, gw1, betaw1, Ww1, bw1);
    k_final<<<4096, 256>>>(idx, Wp2, bp2, gw2, betaw2, Ww2, bw2, out);
}

// round 9
// speedup vs baseline: 1.0060x; 1.0060x over previous
#include <cuda_runtime.h>

#define NPTS 65536
#define NSMP 16
#define NSAMPLES (NPTS * NSMP)
#define CNT ((float)NSAMPLES)
#define EPS 1e-5f

// ---------------- static device scratch ------------------------------------
__device__ float g_xq[NPTS * 64];
__device__ float g_xk[NPTS * 64];
__device__ float g_xv[NPTS * 64];
__device__ float g_w8[NSAMPLES * 8];
__device__ float g_r0[NSAMPLES];   // positional activations, plane per channel
__device__ float g_r1[NSAMPLES];
__device__ float g_r2[NSAMPLES];
__device__ float g_sP[6];          // sum[3], sumsq[3]
__device__ float g_sW1[128];       // sum[64], sumsq[64]
__device__ float g_sW2[16];        // sum[8],  sumsq[8]

// ---------------- f32x2 helpers ---------------------------------------------
typedef unsigned long long ull;
__device__ __forceinline__ ull fma2(ull a, ull b, ull c) {
    ull d;
    asm("fma.rn.f32x2 %0, %1, %2, %3;" : "=l"(d) : "l"(a), "l"(b), "l"(c));
    return d;
}
__device__ __forceinline__ ull dup2(float v) {
    ull d;
    asm("mov.b64 %0, {%1, %1};" : "=l"(d) : "r"(__float_as_uint(v)));
    return d;
}
__device__ __forceinline__ void unpack2(ull v, float& lo, float& hi) {
    unsigned int a, b;
    asm("mov.b64 {%0, %1}, %2;" : "=r"(a), "=r"(b) : "l"(v));
    lo = __uint_as_float(a); hi = __uint_as_float(b);
}

// ---------------- K0: zero stats --------------------------------------------
__global__ void k_zero() {
    int t = threadIdx.x;
    if (t < 6)   g_sP[t]  = 0.f;
    if (t < 128) g_sW1[t] = 0.f;
    if (t < 16)  g_sW2[t] = 0.f;
}

// ---------------- K1: QKV GEMM (f32x2 packed) --------------------------------
// grid (1024, 3); block 256. Tile: 64 points x 64 out-channels.
__global__ __launch_bounds__(256) void k_gemm(
    const float* __restrict__ x,
    const float* __restrict__ Wq, const float* __restrict__ bq,
    const float* __restrict__ Wk, const float* __restrict__ bk,
    const float* __restrict__ Wv, const float* __restrict__ bv) {
    __shared__ float xs[64 * 68];  // [j][point]
    __shared__ float ws[64 * 68];  // [j][outch]
    const int t = threadIdx.x;
    const int m = blockIdx.y;
    const float* W    = (m == 0) ? Wq : ((m == 1) ? Wk : Wv);
    const float* bias = (m == 0) ? bq : ((m == 1) ? bk : bv);
    float* out        = (m == 0) ? g_xq : ((m == 1) ? g_xk : g_xv);
    const int pbase = blockIdx.x * 64;

    for (int e = t; e < 4096; e += 256) {
        int r = e >> 6, j = e & 63;
        xs[j * 68 + r] = x[(pbase + r) * 64 + j];
        ws[j * 68 + r] = W[r * 64 + j];
    }
    __syncthreads();

    const int tx = t & 15;   // channels tx*4 .. +3  (2 packed pairs)
    const int ty = t >> 4;   // points   ty*4 .. +3
    ull acc[4][2];
#pragma unroll
    for (int i = 0; i < 4; i++) { acc[i][0] = 0ULL; acc[i][1] = 0ULL; }

    const float4* xp = (const float4*)(xs + ty * 4);
#pragma unroll 8
    for (int j = 0; j < 64; j++) {
        float4 xv4 = xp[j * 17];
        ulonglong2 w2 = *(const ulonglong2*)(ws + j * 68 + tx * 4);
        ull X;
        X = dup2(xv4.x); acc[0][0] = fma2(X, w2.x, acc[0][0]); acc[0][1] = fma2(X, w2.y, acc[0][1]);
        X = dup2(xv4.y); acc[1][0] = fma2(X, w2.x, acc[1][0]); acc[1][1] = fma2(X, w2.y, acc[1][1]);
        X = dup2(xv4.z); acc[2][0] = fma2(X, w2.x, acc[2][0]); acc[2][1] = fma2(X, w2.y, acc[2][1]);
        X = dup2(xv4.w); acc[3][0] = fma2(X, w2.x, acc[3][0]); acc[3][1] = fma2(X, w2.y, acc[3][1]);
    }

    float4 bo = *(const float4*)(bias + tx * 4);
#pragma unroll
    for (int pp = 0; pp < 4; pp++) {
        float c0, c1, c2, c3;
        unpack2(acc[pp][0], c0, c1);
        unpack2(acc[pp][1], c2, c3);
        *(float4*)(out + (pbase + ty * 4 + pp) * 64 + tx * 4) =
            make_float4(c0 + bo.x, c1 + bo.y, c2 + bo.z, c3 + bo.w);
    }
}

// ---------------- K2: positional pre-BN activations + stats ------------------
// grid 1024; block 256; thread handles 4 consecutive samples.
__global__ __launch_bounds__(256) void k_statsP(
    const float* __restrict__ p, const int* __restrict__ idx,
    const float* __restrict__ Wp1, const float* __restrict__ bp1) {
    float w00 = Wp1[0], w01 = Wp1[1], w02 = Wp1[2];
    float w10 = Wp1[3], w11 = Wp1[4], w12 = Wp1[5];
    float w20 = Wp1[6], w21 = Wp1[7], w22 = Wp1[8];
    float b0 = bp1[0], b1 = bp1[1], b2 = bp1[2];

    float s0 = 0, s1 = 0, s2 = 0, q0 = 0, q1 = 0, q2 = 0;
    int base = (blockIdx.x * 256 + threadIdx.x) * 4;
    int4 jj = *(const int4*)(idx + base);
    int js[4] = {jj.x, jj.y, jj.z, jj.w};
    float o0[4], o1[4], o2[4];
#pragma unroll
    for (int i = 0; i < 4; i++) {
        int sid = base + i;
        int n = sid >> 4;
        int j = js[i];
        float dx = p[j * 3 + 0] - p[n * 3 + 0];
        float dy = p[j * 3 + 1] - p[n * 3 + 1];
        float dz = p[j * 3 + 2] - p[n * 3 + 2];
        float a0 = w00 * dx + w01 * dy + w02 * dz + b0;
        float a1 = w10 * dx + w11 * dy + w12 * dz + b1;
        float a2 = w20 * dx + w21 * dy + w22 * dz + b2;
        o0[i] = a0; o1[i] = a1; o2[i] = a2;
        s0 += a0; s1 += a1; s2 += a2;
        q0 += a0 * a0; q1 += a1 * a1; q2 += a2 * a2;
    }
    *(float4*)(g_r0 + base) = make_float4(o0[0], o0[1], o0[2], o0[3]);
    *(float4*)(g_r1 + base) = make_float4(o1[0], o1[1], o1[2], o1[3]);
    *(float4*)(g_r2 + base) = make_float4(o2[0], o2[1], o2[2], o2[3]);

#pragma unroll
    for (int o = 16; o; o >>= 1) {
        s0 += __shfl_xor_sync(0xffffffffu, s0, o);
        s1 += __shfl_xor_sync(0xffffffffu, s1, o);
        s2 += __shfl_xor_sync(0xffffffffu, s2, o);
        q0 += __shfl_xor_sync(0xffffffffu, q0, o);
        q1 += __shfl_xor_sync(0xffffffffu, q1, o);
        q2 += __shfl_xor_sync(0xffffffffu, q2, o);
    }
    __shared__ float red[8][6];
    int w = threadIdx.x >> 5, lane = threadIdx.x & 31;
    if (lane == 0) {
        red[w][0] = s0; red[w][1] = s1; red[w][2] = s2;
        red[w][3] = q0; red[w][4] = q1; red[w][5] = q2;
    }
    __syncthreads();
    if (threadIdx.x < 6) {
        float acc = 0.f;
#pragma unroll
        for (int i = 0; i < 8; i++) acc += red[i][threadIdx.x];
        atomicAdd(&g_sP[threadIdx.x], acc);
    }
}

// ---------------- K2b: apply BN+ReLU to r planes in place --------------------
// grid (1024, 3); block 256; float4 per thread.
__global__ __launch_bounds__(256) void k_bnp(
    const float* __restrict__ gp, const float* __restrict__ betap) {
    int c = blockIdx.y;
    float m = g_sP[c] / CNT;
    float v = g_sP[3 + c] / CNT - m * m;
    float A = gp[c] * rsqrtf(v + EPS);
    float B = betap[c] - m * A;
    float* r = (c == 0) ? g_r0 : ((c == 1) ? g_r1 : g_r2);
    int i = (blockIdx.x * 256 + threadIdx.x) * 4;
    float4 v4 = *(float4*)(r + i);
    v4.x = fmaxf(A * v4.x + B, 0.f);
    v4.y = fmaxf(A * v4.y + B, 0.f);
    v4.z = fmaxf(A * v4.z + B, 0.f);
    v4.w = fmaxf(A * v4.w + B, 0.f);
    *(float4*)(r + i) = v4;
}

// ---------------- K3: stats of w = xk[idx] - xq + p_r2 -----------------------
// grid 1024; block 256 (8 warps); warp handles 8 points.
__global__ __launch_bounds__(256) void k_statsW1(
    const int* __restrict__ idx,
    const float* __restrict__ Wp2, const float* __restrict__ bp2) {
    __shared__ float sh_r[8][16][3];
    __shared__ int   sh_j[8][16];
    __shared__ float sred[128];
    int t = threadIdx.x, w = t >> 5, l = t & 31;
    if (t < 128) sred[t] = 0.f;

    int c0 = l, c1 = l + 32;
    float wa0 = Wp2[c0 * 3], wa1 = Wp2[c0 * 3 + 1], wa2 = Wp2[c0 * 3 + 2], ba = bp2[c0];
    float wb0 = Wp2[c1 * 3], wb1 = Wp2[c1 * 3 + 1], wb2 = Wp2[c1 * 3 + 2], bb = bp2[c1];

    float s0 = 0, ss0 = 0, s1 = 0, ss1 = 0;
    int pwarp = (blockIdx.x * 8 + w) * 8;
    __syncthreads();

    for (int pt = 0; pt < 8; pt++) {
        int n = pwarp + pt;
        float xq0 = g_xq[n * 64 + c0];
        float xq1 = g_xq[n * 64 + c1];
        if (l < 16) {
            int sid = n * 16 + l;
            sh_j[w][l] = idx[sid];
            sh_r[w][l][0] = g_r0[sid];
            sh_r[w][l][1] = g_r1[sid];
            sh_r[w][l][2] = g_r2[sid];
        }
        __syncwarp();
#pragma unroll
        for (int k = 0; k < 16; k++) {
            int j = sh_j[w][k];
            float r0 = sh_r[w][k][0], r1 = sh_r[w][k][1], r2 = sh_r[w][k][2];
            float pr0 = ba + r0 * wa0 + r1 * wa1 + r2 * wa2;
            float pr1 = bb + r0 * wb0 + r1 * wb1 + r2 * wb2;
            float v0 = g_xk[j * 64 + c0] - xq0 + pr0;
            float v1 = g_xk[j * 64 + c1] - xq1 + pr1;
            s0 += v0; ss0 += v0 * v0;
            s1 += v1; ss1 += v1 * v1;
        }
        __syncwarp();
    }
    atomicAdd(&sred[c0], s0);
    atomicAdd(&sred[64 + c0], ss0);
    atomicAdd(&sred[c1], s1);
    atomicAdd(&sred[64 + c1], ss1);
    __syncthreads();
    if (t < 128) atomicAdd(&g_sW1[t], sred[t]);
}

// ---------------- K4: w8 = relu(bn1(w)) @ Ww1^T + bw1, + stats ---------------
// grid 2048; block 128 (4 warps); warp handles 8 points in 4 tiles of 2.
__global__ __launch_bounds__(128) void k_w8(
    const int* __restrict__ idx,
    const float* __restrict__ Wp2, const float* __restrict__ bp2,
    const float* __restrict__ gw1, const float* __restrict__ betaw1,
    const float* __restrict__ Ww1, const float* __restrict__ bw1) {
    __shared__ float sh_h[4][32 * 68];
    __shared__ float sh_r[4][32][3];
    __shared__ int   sh_j[4][32];
    __shared__ float ww1s[8][64];
    __shared__ float sred2[16];
    int t = threadIdx.x, w = t >> 5, l = t & 31;
    if (t < 16) sred2[t] = 0.f;
    for (int e = t; e < 512; e += 128) ww1s[e >> 6][e & 63] = Ww1[e];

    int c0 = l, c1 = l + 32;
    float wa0 = Wp2[c0 * 3], wa1 = Wp2[c0 * 3 + 1], wa2 = Wp2[c0 * 3 + 2], ba = bp2[c0];
    float wb0 = Wp2[c1 * 3], wb1 = Wp2[c1 * 3 + 1], wb2 = Wp2[c1 * 3 + 2], bb = bp2[c1];

    float m0 = g_sW1[c0] / CNT, v0 = g_sW1[64 + c0] / CNT - m0 * m0;
    float A0 = gw1[c0] * rsqrtf(v0 + EPS), B0 = betaw1[c0] - m0 * A0;
    float m1 = g_sW1[c1] / CNT, v1 = g_sW1[64 + c1] / CNT - m1 * m1;
    float A1 = gw1[c1] * rsqrtf(v1 + EPS), B1 = betaw1[c1] - m1 * A1;

    float bw[8];
#pragma unroll
    for (int r = 0; r < 8; r++) bw[r] = bw1[r];
    float sw[8], sq[8];
#pragma unroll
    for (int r = 0; r < 8; r++) { sw[r] = 0.f; sq[r] = 0.f; }

    int pwarp = (blockIdx.x * 4 + w) * 8;
    __syncthreads();

    for (int tt = 0; tt < 4; tt++) {
        int pA = pwarp + tt * 2;
        {   // stage 2 points x 16 neighbors
            int sid = (pA + (l >> 4)) * 16 + (l & 15);
            sh_j[w][l] = idx[sid];
            sh_r[w][l][0] = g_r0[sid];
            sh_r[w][l][1] = g_r1[sid];
            sh_r[w][l][2] = g_r2[sid];
        }
        float xqA0 = g_xq[pA * 64 + c0],       xqA1 = g_xq[pA * 64 + c1];
        float xqB0 = g_xq[(pA + 1) * 64 + c0], xqB1 = g_xq[(pA + 1) * 64 + c1];
        __syncwarp();
#pragma unroll
        for (int k = 0; k < 32; k++) {
            int j = sh_j[w][k];
            float r0 = sh_r[w][k][0], r1 = sh_r[w][k][1], r2 = sh_r[w][k][2];
            float pr0 = ba + r0 * wa0 + r1 * wa1 + r2 * wa2;
            float pr1 = bb + r0 * wb0 + r1 * wb1 + r2 * wb2;
            float xq0_ = (k < 16) ? xqA0 : xqB0;
            float xq1_ = (k < 16) ? xqA1 : xqB1;
            float u0 = g_xk[j * 64 + c0] - xq0_ + pr0;
            float u1 = g_xk[j * 64 + c1] - xq1_ + pr1;
            sh_h[w][k * 68 + l]      = fmaxf(A0 * u0 + B0, 0.f);
            sh_h[w][k * 68 + l + 32] = fmaxf(A1 * u1 + B1, 0.f);
        }
        __syncwarp();
        // lane <-> sample; matvec 64 -> 8
        float y[8];
#pragma unroll
        for (int r = 0; r < 8; r++) y[r] = bw[r];
        const float4* hv4 = (const float4*)(sh_h[w] + l * 68);
#pragma unroll
        for (int cc = 0; cc < 16; cc++) {
            float4 h4 = hv4[cc];
#pragma unroll
            for (int r = 0; r < 8; r++) {
                float4 w4 = *(const float4*)(&ww1s[r][cc * 4]);
                y[r] += h4.x * w4.x + h4.y * w4.y + h4.z * w4.z + h4.w * w4.w;
            }
        }
        int sid = pA * 16 + l;
        *(float4*)(g_w8 + sid * 8)     = make_float4(y[0], y[1], y[2], y[3]);
        *(float4*)(g_w8 + sid * 8 + 4) = make_float4(y[4], y[5], y[6], y[7]);
#pragma unroll
        for (int r = 0; r < 8; r++) { sw[r] += y[r]; sq[r] += y[r] * y[r]; }
        __syncwarp();
    }
#pragma unroll
    for (int o = 16; o; o >>= 1) {
#pragma unroll
        for (int r = 0; r < 8; r++) {
            sw[r] += __shfl_xor_sync(0xffffffffu, sw[r], o);
            sq[r] += __shfl_xor_sync(0xffffffffu, sq[r], o);
        }
    }
    if (l == 0) {
#pragma unroll
        for (int r = 0; r < 8; r++) {
            atomicAdd(&sred2[r], sw[r]);
            atomicAdd(&sred2[8 + r], sq[r]);
        }
    }
    __syncthreads();
    if (t < 16) atomicAdd(&g_sW2[t], sred2[t]);
}

// ---------------- K5: bn2 + relu + 8x8 matvec + softmax + aggregate ----------
// grid 4096; block 256 (8 warps); warp handles 2 points.
__global__ __launch_bounds__(256) void k_final(
    const int* __restrict__ idx,
    const float* __restrict__ Wp2, const float* __restrict__ bp2,
    const float* __restrict__ gw2, const float* __restrict__ betaw2,
    const float* __restrict__ Ww2, const float* __restrict__ bw2,
    float* __restrict__ out) {
    __shared__ float sh_s[8][32][9];
    __shared__ float sh_r[8][32][3];
    __shared__ int   sh_j[8][32];
    int t = threadIdx.x, w = t >> 5, l = t & 31;

    float A2[8], B2[8];
#pragma unroll
    for (int r = 0; r < 8; r++) {
        float m = g_sW2[r] / CNT;
        float v = g_sW2[8 + r] / CNT - m * m;
        A2[r] = gw2[r] * rsqrtf(v + EPS);
        B2[r] = betaw2[r] - m * A2[r];
    }

    int c0 = l, c1 = l + 32;
    float wa0 = Wp2[c0 * 3], wa1 = Wp2[c0 * 3 + 1], wa2 = Wp2[c0 * 3 + 2], ba = bp2[c0];
    float wb0 = Wp2[c1 * 3], wb1 = Wp2[c1 * 3 + 1], wb2 = Wp2[c1 * 3 + 2], bb = bp2[c1];

    int pbase = (blockIdx.x * 8 + w) * 2;
    int sid = (pbase + (l >> 4)) * 16 + (l & 15);
    sh_j[w][l] = idx[sid];
    sh_r[w][l][0] = g_r0[sid];
    sh_r[w][l][1] = g_r1[sid];
    sh_r[w][l][2] = g_r2[sid];

    float4 y0 = *(const float4*)(g_w8 + sid * 8);
    float4 y1 = *(const float4*)(g_w8 + sid * 8 + 4);
    float h[8] = {y0.x, y0.y, y0.z, y0.w, y1.x, y1.y, y1.z, y1.w};
#pragma unroll
    for (int r = 0; r < 8; r++) h[r] = fmaxf(A2[r] * h[r] + B2[r], 0.f);

    float z[8];
#pragma unroll
    for (int r = 0; r < 8; r++) {
        float acc = bw2[r];
#pragma unroll
        for (int i = 0; i < 8; i++) acc += h[i] * Ww2[r * 8 + i];
        z[r] = acc;
    }
    // softmax over 16 neighbors (xor <= 8 keeps 16-lane halves independent)
#pragma unroll
    for (int r = 0; r < 8; r++) {
        float mx = z[r];
#pragma unroll
        for (int o = 8; o; o >>= 1) mx = fmaxf(mx, __shfl_xor_sync(0xffffffffu, mx, o));
        float e = __expf(z[r] - mx);
        float sm = e;
#pragma unroll
        for (int o = 8; o; o >>= 1) sm += __shfl_xor_sync(0xffffffffu, sm, o);
        sh_s[w][l][r] = e / sm;
    }
    __syncwarp();
#pragma unroll
    for (int pp = 0; pp < 2; pp++) {
        int n = pbase + pp;
        float acc0 = 0.f, acc1 = 0.f;
#pragma unroll
        for (int k = 0; k < 16; k++) {
            int kk = pp * 16 + k;
            int jg = sh_j[w][kk];
            float r0 = sh_r[w][kk][0], r1 = sh_r[w][kk][1], r2 = sh_r[w][kk][2];
            float pr0 = ba + r0 * wa0 + r1 * wa1 + r2 * wa2;
            float pr1 = bb + r0 * wb0 + r1 * wb1 + r2 * wb2;
            float s8 = sh_s[w][kk][l & 7];
            acc0 += (g_xv[jg * 64 + c0] + pr0) * s8;
            acc1 += (g_xv[jg * 64 + c1] + pr1) * s8;
        }
        out[n * 64 + c0] = acc0;
        out[n * 64 + c1] = acc1;
    }
}

// ---------------- launch ------------------------------------------------------
extern "C" void kernel_launch(void* const* d_in, const int* in_sizes, int n_in,
                              void* d_out, int out_size) {
    const float* p     = (const float*)d_in[0];
    const float* x     = (const float*)d_in[1];
    const int*   idx   = (const int*)d_in[2];
    const float* Wq    = (const float*)d_in[3];
    const float* bq    = (const float*)d_in[4];
    const float* Wk    = (const float*)d_in[5];
    const float* bk    = (const float*)d_in[6];
    const float* Wv    = (const float*)d_in[7];
    const float* bv    = (const float*)d_in[8];
    const float* Wp1   = (const float*)d_in[9];
    const float* bp1   = (const float*)d_in[10];
    const float* gp    = (const float*)d_in[11];
    const float* betap = (const float*)d_in[12];
    const float* Wp2   = (const float*)d_in[13];
    const float* bp2   = (const float*)d_in[14];
    const float* gw1   = (const float*)d_in[15];
    const float* betaw1= (const float*)d_in[16];
    const float* Ww1   = (const float*)d_in[17];
    const float* bw1   = (const float*)d_in[18];
    const float* gw2   = (const float*)d_in[19];
    const float* betaw2= (const float*)d_in[20];
    const float* Ww2   = (const float*)d_in[21];
    const float* bw2   = (const float*)d_in[22];
    float* out = (float*)d_out;

    k_zero<<<1, 128>>>();
    dim3 g1(1024, 3);
    k_gemm<<<g1, 256>>>(x, Wq, bq, Wk, bk, Wv, bv);
    k_statsP<<<1024, 256>>>(p, idx, Wp1, bp1);
    dim3 g2(1024, 3);
    k_bnp<<<g2, 256>>>(gp, betap);
    k_statsW1<<<1024, 256>>>(idx, Wp2, bp2);
    k_w8<<<2048, 128>>>(idx, Wp2, bp2, gw1, betaw1, Ww1, bw1);
    k_final<<<4096, 256>>>(idx, Wp2, bp2, gw2, betaw2, Ww2, bw2, out);
}

// round 10
// speedup vs baseline: 1.0665x; 1.0601x over previous
#include <cuda_runtime.h>

#define NPTS 65536
#define NSMP 16
#define NSAMPLES (NPTS * NSMP)
#define CNT ((float)NSAMPLES)
#define EPS 1e-5f

// ---------------- static device scratch ------------------------------------
__device__ float g_xq[NPTS * 64];
__device__ float g_xk[NPTS * 64];
__device__ float g_xv[NPTS * 64];
__device__ float g_w8[NSAMPLES * 8];
__device__ float g_r0[NSAMPLES];   // positional pre-BN activations (planar)
__device__ float g_r1[NSAMPLES];
__device__ float g_r2[NSAMPLES];
__device__ float g_sP[6];          // sum[3], sumsq[3]
__device__ float g_sW1[128];       // sum[64], sumsq[64]
__device__ float g_sW2[16];        // sum[8],  sumsq[8]

// ---------------- f32x2 helpers ---------------------------------------------
typedef unsigned long long ull;
__device__ __forceinline__ ull fma2(ull a, ull b, ull c) {
    ull d;
    asm("fma.rn.f32x2 %0, %1, %2, %3;" : "=l"(d) : "l"(a), "l"(b), "l"(c));
    return d;
}
__device__ __forceinline__ ull add2(ull a, ull b) {
    ull d;
    asm("add.rn.f32x2 %0, %1, %2;" : "=l"(d) : "l"(a), "l"(b));
    return d;
}
__device__ __forceinline__ ull dup2(float v) {
    ull d;
    asm("mov.b64 %0, {%1, %1};" : "=l"(d) : "r"(__float_as_uint(v)));
    return d;
}
__device__ __forceinline__ ull pack2(float lo, float hi) {
    ull d;
    asm("mov.b64 %0, {%1, %2};" : "=l"(d) : "r"(__float_as_uint(lo)), "r"(__float_as_uint(hi)));
    return d;
}
__device__ __forceinline__ void unpack2(ull v, float& lo, float& hi) {
    unsigned int a, b;
    asm("mov.b64 {%0, %1}, %2;" : "=r"(a), "=r"(b) : "l"(v));
    lo = __uint_as_float(a); hi = __uint_as_float(b);
}

// ---------------- K0: zero stats --------------------------------------------
__global__ void k_zero() {
    int t = threadIdx.x;
    if (t < 6)   g_sP[t]  = 0.f;
    if (t < 128) g_sW1[t] = 0.f;
    if (t < 16)  g_sW2[t] = 0.f;
}

// ---------------- K1: QKV GEMM (f32x2 packed) --------------------------------
__global__ __launch_bounds__(256) void k_gemm(
    const float* __restrict__ x,
    const float* __restrict__ Wq, const float* __restrict__ bq,
    const float* __restrict__ Wk, const float* __restrict__ bk,
    const float* __restrict__ Wv, const float* __restrict__ bv) {
    __shared__ __align__(16) float xs[64 * 68];
    __shared__ __align__(16) float ws[64 * 68];
    const int t = threadIdx.x;
    const int m = blockIdx.y;
    const float* W    = (m == 0) ? Wq : ((m == 1) ? Wk : Wv);
    const float* bias = (m == 0) ? bq : ((m == 1) ? bk : bv);
    float* out        = (m == 0) ? g_xq : ((m == 1) ? g_xk : g_xv);
    const int pbase = blockIdx.x * 64;

    for (int e = t; e < 4096; e += 256) {
        int r = e >> 6, j = e & 63;
        xs[j * 68 + r] = x[(pbase + r) * 64 + j];
        ws[j * 68 + r] = W[r * 64 + j];
    }
    __syncthreads();

    const int tx = t & 15;
    const int ty = t >> 4;
    ull acc[4][2];
#pragma unroll
    for (int i = 0; i < 4; i++) { acc[i][0] = 0ULL; acc[i][1] = 0ULL; }

    const float4* xp = (const float4*)(xs + ty * 4);
#pragma unroll 8
    for (int j = 0; j < 64; j++) {
        float4 xv4 = xp[j * 17];
        ulonglong2 w2 = *(const ulonglong2*)(ws + j * 68 + tx * 4);
        ull X;
        X = dup2(xv4.x); acc[0][0] = fma2(X, w2.x, acc[0][0]); acc[0][1] = fma2(X, w2.y, acc[0][1]);
        X = dup2(xv4.y); acc[1][0] = fma2(X, w2.x, acc[1][0]); acc[1][1] = fma2(X, w2.y, acc[1][1]);
        X = dup2(xv4.z); acc[2][0] = fma2(X, w2.x, acc[2][0]); acc[2][1] = fma2(X, w2.y, acc[2][1]);
        X = dup2(xv4.w); acc[3][0] = fma2(X, w2.x, acc[3][0]); acc[3][1] = fma2(X, w2.y, acc[3][1]);
    }

    float4 bo = *(const float4*)(bias + tx * 4);
#pragma unroll
    for (int pp = 0; pp < 4; pp++) {
        float c0, c1, c2, c3;
        unpack2(acc[pp][0], c0, c1);
        unpack2(acc[pp][1], c2, c3);
        *(float4*)(out + (pbase + ty * 4 + pp) * 64 + tx * 4) =
            make_float4(c0 + bo.x, c1 + bo.y, c2 + bo.z, c3 + bo.w);
    }
}

// ---------------- K2: positional pre-BN activations + stats ------------------
__global__ __launch_bounds__(256) void k_statsP(
    const float* __restrict__ p, const int* __restrict__ idx,
    const float* __restrict__ Wp1, const float* __restrict__ bp1) {
    float w00 = Wp1[0], w01 = Wp1[1], w02 = Wp1[2];
    float w10 = Wp1[3], w11 = Wp1[4], w12 = Wp1[5];
    float w20 = Wp1[6], w21 = Wp1[7], w22 = Wp1[8];
    float b0 = bp1[0], b1 = bp1[1], b2 = bp1[2];

    float s0 = 0, s1 = 0, s2 = 0, q0 = 0, q1 = 0, q2 = 0;
    int base = (blockIdx.x * 256 + threadIdx.x) * 4;
    int4 jj = *(const int4*)(idx + base);
    int js[4] = {jj.x, jj.y, jj.z, jj.w};
    float o0[4], o1[4], o2[4];
#pragma unroll
    for (int i = 0; i < 4; i++) {
        int sid = base + i;
        int n = sid >> 4;
        int j = js[i];
        float dx = p[j * 3 + 0] - p[n * 3 + 0];
        float dy = p[j * 3 + 1] - p[n * 3 + 1];
        float dz = p[j * 3 + 2] - p[n * 3 + 2];
        float a0 = w00 * dx + w01 * dy + w02 * dz + b0;
        float a1 = w10 * dx + w11 * dy + w12 * dz + b1;
        float a2 = w20 * dx + w21 * dy + w22 * dz + b2;
        o0[i] = a0; o1[i] = a1; o2[i] = a2;
        s0 += a0; s1 += a1; s2 += a2;
        q0 += a0 * a0; q1 += a1 * a1; q2 += a2 * a2;
    }
    *(float4*)(g_r0 + base) = make_float4(o0[0], o0[1], o0[2], o0[3]);
    *(float4*)(g_r1 + base) = make_float4(o1[0], o1[1], o1[2], o1[3]);
    *(float4*)(g_r2 + base) = make_float4(o2[0], o2[1], o2[2], o2[3]);

#pragma unroll
    for (int o = 16; o; o >>= 1) {
        s0 += __shfl_xor_sync(0xffffffffu, s0, o);
        s1 += __shfl_xor_sync(0xffffffffu, s1, o);
        s2 += __shfl_xor_sync(0xffffffffu, s2, o);
        q0 += __shfl_xor_sync(0xffffffffu, q0, o);
        q1 += __shfl_xor_sync(0xffffffffu, q1, o);
        q2 += __shfl_xor_sync(0xffffffffu, q2, o);
    }
    __shared__ float red[8][6];
    int w = threadIdx.x >> 5, lane = threadIdx.x & 31;
    if (lane == 0) {
        red[w][0] = s0; red[w][1] = s1; red[w][2] = s2;
        red[w][3] = q0; red[w][4] = q1; red[w][5] = q2;
    }
    __syncthreads();
    if (threadIdx.x < 6) {
        float acc = 0.f;
#pragma unroll
        for (int i = 0; i < 8; i++) acc += red[i][threadIdx.x];
        atomicAdd(&g_sP[threadIdx.x], acc);
    }
}

// ---------------- BN-P constants (inline helper) -----------------------------
__device__ __forceinline__ void bnp_coef(const float* gp, const float* betap,
                                         float* aP, float* bP) {
#pragma unroll
    for (int c = 0; c < 3; c++) {
        float m = g_sP[c] / CNT;
        float v = g_sP[3 + c] / CNT - m * m;
        aP[c] = gp[c] * rsqrtf(v + EPS);
        bP[c] = betap[c] - m * aP[c];
    }
}

// ---------------- K3: stats of w = xk[idx] - xq + p_r2 (packed) --------------
// grid 1024; block 256 (8 warps); warp handles 8 points in 4 tiles of 2.
// Lane l owns channels (2l, 2l+1).
__global__ __launch_bounds__(256) void k_statsW1(
    const int* __restrict__ idx,
    const float* __restrict__ Wp2, const float* __restrict__ bp2,
    const float* __restrict__ gp, const float* __restrict__ betap) {
    __shared__ float sh_r[8][32][3];
    __shared__ int   sh_j[8][32];
    __shared__ float sred[128];
    int t = threadIdx.x, w = t >> 5, l = t & 31;
    if (t < 128) sred[t] = 0.f;

    float aP[3], bP[3];
    bnp_coef(gp, betap, aP, bP);

    const int c0 = 2 * l;
    ull WA0 = pack2(Wp2[c0 * 3],     Wp2[(c0 + 1) * 3]);
    ull WA1 = pack2(Wp2[c0 * 3 + 1], Wp2[(c0 + 1) * 3 + 1]);
    ull WA2 = pack2(Wp2[c0 * 3 + 2], Wp2[(c0 + 1) * 3 + 2]);
    float bq0 = bp2[c0], bq1 = bp2[c0 + 1];

    ull S = 0ULL, SS = 0ULL;
    int pwarp = (blockIdx.x * 8 + w) * 8;
    __syncthreads();

    for (int tt = 0; tt < 4; tt++) {
        int pA = pwarp + tt * 2;
        {   // stage 2 points x 16 neighbors with BN-P + ReLU applied
            int sid = (pA + (l >> 4)) * 16 + (l & 15);
            sh_j[w][l] = idx[sid];
            sh_r[w][l][0] = fmaxf(aP[0] * g_r0[sid] + bP[0], 0.f);
            sh_r[w][l][1] = fmaxf(aP[1] * g_r1[sid] + bP[1], 0.f);
            sh_r[w][l][2] = fmaxf(aP[2] * g_r2[sid] + bP[2], 0.f);
        }
        __syncwarp();
#pragma unroll
        for (int pp = 0; pp < 2; pp++) {
            int n = pA + pp;
            float2 q2 = *(const float2*)(g_xq + n * 64 + c0);
            ull base = pack2(bq0 - q2.x, bq1 - q2.y);
#pragma unroll
            for (int k = 0; k < 16; k++) {
                int kk = pp * 16 + k;
                int j = sh_j[w][kk];
                ull r0d = dup2(sh_r[w][kk][0]);
                ull r1d = dup2(sh_r[w][kk][1]);
                ull r2d = dup2(sh_r[w][kk][2]);
                ull pr = fma2(r2d, WA2, fma2(r1d, WA1, fma2(r0d, WA0, base)));
                ull xk2 = *(const ull*)(g_xk + j * 64 + c0);
                ull wv = add2(xk2, pr);
                S  = add2(S, wv);
                SS = fma2(wv, wv, SS);
            }
        }
        __syncwarp();
    }
    float s0, s1, q0, q1;
    unpack2(S, s0, s1);
    unpack2(SS, q0, q1);
    atomicAdd(&sred[c0], s0);
    atomicAdd(&sred[c0 + 1], s1);
    atomicAdd(&sred[64 + c0], q0);
    atomicAdd(&sred[64 + c0 + 1], q1);
    __syncthreads();
    if (t < 128) atomicAdd(&g_sW1[t], sred[t]);
}

// ---------------- K4: w8 = relu(bn1(w)) @ Ww1^T + bw1, + stats (packed) ------
// grid 2048; block 128 (4 warps); warp handles 8 points in 4 tiles of 2.
__global__ __launch_bounds__(128) void k_w8(
    const int* __restrict__ idx,
    const float* __restrict__ Wp2, const float* __restrict__ bp2,
    const float* __restrict__ gp, const float* __restrict__ betap,
    const float* __restrict__ gw1, const float* __restrict__ betaw1,
    const float* __restrict__ Ww1, const float* __restrict__ bw1) {
    __shared__ __align__(16) float sh_h[4][32 * 68];
    __shared__ float sh_r[4][32][3];
    __shared__ int   sh_j[4][32];
    __shared__ __align__(16) float ww1s[8][64];
    __shared__ float sred2[16];
    int t = threadIdx.x, w = t >> 5, l = t & 31;
    if (t < 16) sred2[t] = 0.f;
    for (int e = t; e < 512; e += 128) ww1s[e >> 6][e & 63] = Ww1[e];

    float aP[3], bP[3];
    bnp_coef(gp, betap, aP, bP);

    const int c0 = 2 * l;
    ull WA0 = pack2(Wp2[c0 * 3],     Wp2[(c0 + 1) * 3]);
    ull WA1 = pack2(Wp2[c0 * 3 + 1], Wp2[(c0 + 1) * 3 + 1]);
    ull WA2 = pack2(Wp2[c0 * 3 + 2], Wp2[(c0 + 1) * 3 + 2]);
    float bq0 = bp2[c0], bq1 = bp2[c0 + 1];

    // BN1 coefficients for channel pair
    float m0 = g_sW1[c0] / CNT,     v0 = g_sW1[64 + c0] / CNT - m0 * m0;
    float A0 = gw1[c0] * rsqrtf(v0 + EPS), B0 = betaw1[c0] - m0 * A0;
    float m1 = g_sW1[c0 + 1] / CNT, v1 = g_sW1[64 + c0 + 1] / CNT - m1 * m1;
    float A1 = gw1[c0 + 1] * rsqrtf(v1 + EPS), B1 = betaw1[c0 + 1] - m1 * A1;
    ull A1p = pack2(A0, A1), B1p = pack2(B0, B1);

    float bw[8];
#pragma unroll
    for (int r = 0; r < 8; r++) bw[r] = bw1[r];
    float sw[8], sq[8];
#pragma unroll
    for (int r = 0; r < 8; r++) { sw[r] = 0.f; sq[r] = 0.f; }

    int pwarp = (blockIdx.x * 4 + w) * 8;
    __syncthreads();

    for (int tt = 0; tt < 4; tt++) {
        int pA = pwarp + tt * 2;
        {   // stage 2 points x 16 neighbors (BN-P + ReLU applied)
            int sid = (pA + (l >> 4)) * 16 + (l & 15);
            sh_j[w][l] = idx[sid];
            sh_r[w][l][0] = fmaxf(aP[0] * g_r0[sid] + bP[0], 0.f);
            sh_r[w][l][1] = fmaxf(aP[1] * g_r1[sid] + bP[1], 0.f);
            sh_r[w][l][2] = fmaxf(aP[2] * g_r2[sid] + bP[2], 0.f);
        }
        float2 qA = *(const float2*)(g_xq + pA * 64 + c0);
        float2 qB = *(const float2*)(g_xq + (pA + 1) * 64 + c0);
        ull base0 = pack2(bq0 - qA.x, bq1 - qA.y);
        ull base1 = pack2(bq0 - qB.x, bq1 - qB.y);
        __syncwarp();
        // phase A: h = relu(bn1(w)) into shared, sample-major rows
#pragma unroll
        for (int kk = 0; kk < 32; kk++) {
            int j = sh_j[w][kk];
            ull r0d = dup2(sh_r[w][kk][0]);
            ull r1d = dup2(sh_r[w][kk][1]);
            ull r2d = dup2(sh_r[w][kk][2]);
            ull base = (kk < 16) ? base0 : base1;
            ull pr = fma2(r2d, WA2, fma2(r1d, WA1, fma2(r0d, WA0, base)));
            ull xk2 = *(const ull*)(g_xk + j * 64 + c0);
            ull u = add2(xk2, pr);
            ull hp = fma2(A1p, u, B1p);
            float h0, h1;
            unpack2(hp, h0, h1);
            h0 = fmaxf(h0, 0.f); h1 = fmaxf(h1, 0.f);
            *(ull*)(sh_h[w] + kk * 68 + c0) = pack2(h0, h1);
        }
        __syncwarp();
        // phase B: lane <-> sample; matvec 64 -> 8 with packed FMA
        ull Y[8];
#pragma unroll
        for (int r = 0; r < 8; r++) Y[r] = 0ULL;
        const ulonglong2* hv = (const ulonglong2*)(sh_h[w] + l * 68);
#pragma unroll
        for (int cc = 0; cc < 16; cc++) {
            ulonglong2 h2 = hv[cc];
#pragma unroll
            for (int r = 0; r < 8; r++) {
                ulonglong2 w2 = *(const ulonglong2*)(&ww1s[r][cc * 4]);
                Y[r] = fma2(h2.x, w2.x, Y[r]);
                Y[r] = fma2(h2.y, w2.y, Y[r]);
            }
        }
        float y[8];
#pragma unroll
        for (int r = 0; r < 8; r++) {
            float a, b;
            unpack2(Y[r], a, b);
            y[r] = bw[r] + a + b;
        }
        int sid = pA * 16 + l;
        *(float4*)(g_w8 + sid * 8)     = make_float4(y[0], y[1], y[2], y[3]);
        *(float4*)(g_w8 + sid * 8 + 4) = make_float4(y[4], y[5], y[6], y[7]);
#pragma unroll
        for (int r = 0; r < 8; r++) { sw[r] += y[r]; sq[r] += y[r] * y[r]; }
        __syncwarp();
    }
#pragma unroll
    for (int o = 16; o; o >>= 1) {
#pragma unroll
        for (int r = 0; r < 8; r++) {
            sw[r] += __shfl_xor_sync(0xffffffffu, sw[r], o);
            sq[r] += __shfl_xor_sync(0xffffffffu, sq[r], o);
        }
    }
    if (l == 0) {
#pragma unroll
        for (int r = 0; r < 8; r++) {
            atomicAdd(&sred2[r], sw[r]);
            atomicAdd(&sred2[8 + r], sq[r]);
        }
    }
    __syncthreads();
    if (t < 16) atomicAdd(&g_sW2[t], sred2[t]);
}

// ---------------- K5: bn2 + relu + 8x8 matvec + softmax + aggregate (packed) -
// grid 4096; block 256 (8 warps); warp handles 2 points.
__global__ __launch_bounds__(256) void k_final(
    const int* __restrict__ idx,
    const float* __restrict__ Wp2, const float* __restrict__ bp2,
    const float* __restrict__ gp, const float* __restrict__ betap,
    const float* __restrict__ gw2, const float* __restrict__ betaw2,
    const float* __restrict__ Ww2, const float* __restrict__ bw2,
    float* __restrict__ out) {
    __shared__ __align__(16) float sh_s[8][32 * 10];
    __shared__ float sh_r[8][32][3];
    __shared__ int   sh_j[8][32];
    int t = threadIdx.x, w = t >> 5, l = t & 31;

    float aP[3], bP[3];
    bnp_coef(gp, betap, aP, bP);

    float A2[8], B2[8];
#pragma unroll
    for (int r = 0; r < 8; r++) {
        float m = g_sW2[r] / CNT;
        float v = g_sW2[8 + r] / CNT - m * m;
        A2[r] = gw2[r] * rsqrtf(v + EPS);
        B2[r] = betaw2[r] - m * A2[r];
    }

    const int c0 = 2 * l;
    ull WA0 = pack2(Wp2[c0 * 3],     Wp2[(c0 + 1) * 3]);
    ull WA1 = pack2(Wp2[c0 * 3 + 1], Wp2[(c0 + 1) * 3 + 1]);
    ull WA2 = pack2(Wp2[c0 * 3 + 2], Wp2[(c0 + 1) * 3 + 2]);
    ull BBp = pack2(bp2[c0], bp2[c0 + 1]);

    int pbase = (blockIdx.x * 8 + w) * 2;
    int sid = (pbase + (l >> 4)) * 16 + (l & 15);
    sh_j[w][l] = idx[sid];
    sh_r[w][l][0] = fmaxf(aP[0] * g_r0[sid] + bP[0], 0.f);
    sh_r[w][l][1] = fmaxf(aP[1] * g_r1[sid] + bP[1], 0.f);
    sh_r[w][l][2] = fmaxf(aP[2] * g_r2[sid] + bP[2], 0.f);

    float4 y0 = *(const float4*)(g_w8 + sid * 8);
    float4 y1 = *(const float4*)(g_w8 + sid * 8 + 4);
    float h[8] = {y0.x, y0.y, y0.z, y0.w, y1.x, y1.y, y1.z, y1.w};
#pragma unroll
    for (int r = 0; r < 8; r++) h[r] = fmaxf(A2[r] * h[r] + B2[r], 0.f);

    float z[8];
#pragma unroll
    for (int r = 0; r < 8; r++) {
        float acc = bw2[r];
#pragma unroll
        for (int i = 0; i < 8; i++) acc += h[i] * Ww2[r * 8 + i];
        z[r] = acc;
    }
    // softmax over 16 neighbors (xor <= 8 keeps 16-lane halves independent)
#pragma unroll
    for (int r = 0; r < 8; r++) {
        float mx = z[r];
#pragma unroll
        for (int o = 8; o; o >>= 1) mx = fmaxf(mx, __shfl_xor_sync(0xffffffffu, mx, o));
        float e = __expf(z[r] - mx);
        float sm = e;
#pragma unroll
        for (int o = 8; o; o >>= 1) sm += __shfl_xor_sync(0xffffffffu, sm, o);
        sh_s[w][l * 10 + r] = e / sm;
    }
    __syncwarp();
    // aggregate: lane l owns channels (2l, 2l+1); packed loads/FMA
#pragma unroll
    for (int pp = 0; pp < 2; pp++) {
        int n = pbase + pp;
        ull ACC = 0ULL;
#pragma unroll
        for (int k = 0; k < 16; k++) {
            int kk = pp * 16 + k;
            int jg = sh_j[w][kk];
            ull r0d = dup2(sh_r[w][kk][0]);
            ull r1d = dup2(sh_r[w][kk][1]);
            ull r2d = dup2(sh_r[w][kk][2]);
            ull pr = fma2(r2d, WA2, fma2(r1d, WA1, fma2(r0d, WA0, BBp)));
            ull xv2 = *(const ull*)(g_xv + jg * 64 + c0);
            ull tv = add2(xv2, pr);
            ull s2 = *(const ull*)(sh_s[w] + kk * 10 + (c0 & 7));
            ACC = fma2(tv, s2, ACC);
        }
        float a0, a1;
        unpack2(ACC, a0, a1);
        *(float2*)(out + n * 64 + c0) = make_float2(a0, a1);
    }
}

// ---------------- launch ------------------------------------------------------
extern "C" void kernel_launch(void* const* d_in, const int* in_sizes, int n_in,
                              void* d_out, int out_size) {
    const float* p     = (const float*)d_in[0];
    const float* x     = (const float*)d_in[1];
    const int*   idx   = (const int*)d_in[2];
    const float* Wq    = (const float*)d_in[3];
    const float* bq    = (const float*)d_in[4];
    const float* Wk    = (const float*)d_in[5];
    const float* bk    = (const float*)d_in[6];
    const float* Wv    = (const float*)d_in[7];
    const float* bv    = (const float*)d_in[8];
    const float* Wp1   = (const float*)d_in[9];
    const float* bp1   = (const float*)d_in[10];
    const float* gp    = (const float*)d_in[11];
    const float* betap = (const float*)d_in[12];
    const float* Wp2   = (const float*)d_in[13];
    const float* bp2   = (const float*)d_in[14];
    const float* gw1   = (const float*)d_in[15];
    const float* betaw1= (const float*)d_in[16];
    const float* Ww1   = (const float*)d_in[17];
    const float* bw1   = (const float*)d_in[18];
    const float* gw2   = (const float*)d_in[19];
    const float* betaw2= (const float*)d_in[20];
    const float* Ww2   = (const float*)d_in[21];
    const float* bw2   = (const float*)d_in[22];
    float* out = (float*)d_out;

    k_zero<<<1, 128>>>();
    dim3 g1(1024, 3);
    k_gemm<<<g1, 256>>>(x, Wq, bq, Wk, bk, Wv, bv);
    k_statsP<<<1024, 256>>>(p, idx, Wp1, bp1);
    k_statsW1<<<1024, 256>>>(idx, Wp2, bp2, gp, betap);
    k_w8<<<2048, 128>>>(idx, Wp2, bp2, gp, betap, gw1, betaw1, Ww1, bw1);
    k_final<<<4096, 256>>>(idx, Wp2, bp2, gp, betap, gw2, betaw2, Ww2, bw2, out);
}